// round 16
// baseline (speedup 1.0000x reference)
#include <cuda_runtime.h>
#include <cuda_bf16.h>
#include <cuda_fp16.h>
#include <cstdint>

typedef __nv_bfloat16 bf16;

#define BSZ 64
#define TT  512
#define FF  1024
#define HH  1024
#define GG  4096
#define KK  1024
#define MTOT (TT*BSZ)   // 32768

// ---------------- device scratch ----------------
__device__ __align__(16) __half g_wih0[GG * KK];       // [G][K] fp16 single plane (xgemm)
__device__ __align__(16) __half g_wih1[GG * KK];
__device__ __align__(16) __half g_whh0[GG * 2 * KK];   // [G][hi | lo*1024] fp16 (recur)
__device__ __align__(16) __half g_whh1[GG * 2 * KK];
__device__ __align__(16) float  g_bias0[GG];
__device__ __align__(16) float  g_bias1[GG];
__device__ __align__(16) float  g_gx[(size_t)MTOT * GG];   // gates_x (512 MB)
__device__ __align__(16) __half g_ax[(size_t)MTOT * KK];   // fp16 A for xgemm (64 MB)
// h in mma-fragment layout (fp16x2, single plane):
//   u32 idx(mblk, kt, lane, reg) = mblk*8192 + kt*128 + lane*4 + reg   (mblk: 16-batch block)
__device__ __align__(16) unsigned g_hf[2][32768];

// grid-barrier flags: monotonic, never reset (deterministic across graph replays)
__device__ volatile unsigned g_flags[128];

// ---------------- generic helpers ----------------
__device__ __forceinline__ void mma_f16(float acc[4], const unsigned a[4], unsigned b0, unsigned b1) {
    asm volatile(
        "mma.sync.aligned.m16n8k16.row.col.f32.f16.f16.f32 "
        "{%0,%1,%2,%3},{%4,%5,%6,%7},{%8,%9},{%0,%1,%2,%3};\n"
        : "+f"(acc[0]), "+f"(acc[1]), "+f"(acc[2]), "+f"(acc[3])
        : "r"(a[0]), "r"(a[1]), "r"(a[2]), "r"(a[3]), "r"(b0), "r"(b1));
}

__device__ __forceinline__ void ldsm4(unsigned r[4], const void* p) {
    unsigned addr = (unsigned)__cvta_generic_to_shared(p);
    asm volatile("ldmatrix.sync.aligned.m8n8.x4.shared.b16 {%0,%1,%2,%3},[%4];\n"
                 : "=r"(r[0]), "=r"(r[1]), "=r"(r[2]), "=r"(r[3]) : "r"(addr));
}

__device__ __forceinline__ void ldg_cg4(unsigned r[4], const void* p) {
    asm volatile("ld.global.cg.v4.u32 {%0,%1,%2,%3}, [%4];\n"
                 : "=r"(r[0]), "=r"(r[1]), "=r"(r[2]), "=r"(r[3]) : "l"(p));
}

__device__ __forceinline__ void st_rel(volatile unsigned* p, unsigned v) {
    asm volatile("st.release.gpu.global.u32 [%0], %1;\n" :: "l"((void*)p), "r"(v) : "memory");
}
__device__ __forceinline__ unsigned ld_acq(volatile unsigned* p) {
    unsigned v;
    asm volatile("ld.acquire.gpu.global.u32 %0, [%1];\n" : "=r"(v) : "l"((void*)p) : "memory");
    return v;
}

__device__ __forceinline__ void cpa16(void* dst, const void* src) {
    unsigned d = (unsigned)__cvta_generic_to_shared(dst);
    asm volatile("cp.async.cg.shared.global [%0], [%1], 16;\n" :: "r"(d), "l"(src));
}
#define CPCOMMIT() asm volatile("cp.async.commit_group;\n")
#define CPWAIT(n)  asm volatile("cp.async.wait_group %0;\n" :: "n"(n))

__device__ __forceinline__ float sigf(float x) { return 1.0f / (1.0f + expf(-x)); }

// ---------------- prep: all weights + biases in ONE launch ----------------
// wih -> fp16 single plane; whh -> fp16 hi + (lo*1024). Masks are 32-bit words.
__global__ void prep_all(const float* __restrict__ w0, const unsigned* __restrict__ m0,
                         const float* __restrict__ w1, const unsigned* __restrict__ m1,
                         const float* __restrict__ w2, const unsigned* __restrict__ m2,
                         const float* __restrict__ w3, const unsigned* __restrict__ m3,
                         const float* __restrict__ bi0, const float* __restrict__ bh0,
                         const float* __restrict__ bi1, const float* __restrict__ bh1) {
    int blk = blockIdx.x;
    if (blk < 65536) {
        int which = blk >> 14;
        int idx = (blk & 16383) * 256 + threadIdx.x;
        const float*    w = (which == 0) ? w0 : (which == 1) ? w1 : (which == 2) ? w2 : w3;
        const unsigned* m = (which == 0) ? m0 : (which == 1) ? m1 : (which == 2) ? m2 : m3;
        int g = idx >> 10, k = idx & 1023;
        float v = (m[idx] != 0u) ? w[idx] : 0.0f;
        __half hi = __float2half_rn(v);
        if (which == 1 || which == 3) {            // whh: 2-plane
            __half* dst = (which == 1) ? g_whh0 : g_whh1;
            float r = (v - __half2float(hi)) * 1024.0f;
            dst[(size_t)g * 2048 + k]        = hi;
            dst[(size_t)g * 2048 + 1024 + k] = __float2half_rn(r);
        } else {                                   // wih: single plane
            __half* dst = (which == 0) ? g_wih0 : g_wih1;
            dst[(size_t)g * 1024 + k] = hi;
        }
    } else {
        for (int i = threadIdx.x; i < GG; i += 256) {
            g_bias0[i] = bi0[i] + bh0[i];
            g_bias1[i] = bi1[i] + bh1[i];
        }
    }
}

// ---------------- prep: x -> g_ax fp16 rows (m = t*64 + b) ----------------
__global__ void prep_ax(const float* __restrict__ x) {
    int m = blockIdx.x * 2 + (threadIdx.x >> 7);
    int c = (threadIdx.x & 127) * 8;
    const float* src = x + ((size_t)(m & 63) * TT + (m >> 6)) * FF + c;
    float4 v0 = *(const float4*)src;
    float4 v1 = *(const float4*)(src + 4);
    __half2 h0 = __halves2half2(__float2half_rn(v0.x), __float2half_rn(v0.y));
    __half2 h1 = __halves2half2(__float2half_rn(v0.z), __float2half_rn(v0.w));
    __half2 h2 = __halves2half2(__float2half_rn(v1.x), __float2half_rn(v1.y));
    __half2 h3 = __halves2half2(__float2half_rn(v1.z), __float2half_rn(v1.w));
    *(uint4*)(g_ax + (size_t)m * 1024 + c) =
        make_uint4(*(unsigned*)&h0, *(unsigned*)&h1, *(unsigned*)&h2, *(unsigned*)&h3);
}

// ---------------- big input GEMM: gates_x = A @ W^T + bias (fp16 single product) ----------------
// A = g_ax [32768][1024] fp16; W = g_wih [4096][1024] fp16; C = g_gx fp32.
// CTA tile 256(M) x 128(N); 512 threads / 16 warps in 4(m) x 4(n); warp tile 64x32.
// K chunks of 64 (128-B rows), cp.async THREE-stage pipeline. Buffers: A(256 rows), B(128 rows).
#define XP 72                    // smem row pitch (fp16)
#define ABUF (256 * XP)          // A buffer (elems)
#define BBUF (128 * XP)          // B buffer (elems)
#define XSTAGE (ABUF + BBUF)
#define XSMEM (3 * XSTAGE * 2)   // bytes = 165888

__device__ __forceinline__ void xload(__half* st, const __half* Abase, const __half* Bbase,
                                      int ck, int tid) {
    // A: 2048 16B units (256 rows x 8 segs)
    #pragma unroll
    for (int i = 0; i < 4; i++) {
        int j = tid + i * 512;
        int row = j >> 3, seg = j & 7;
        cpa16(st + row * XP + seg * 8, Abase + (size_t)row * 1024 + ck * 64 + seg * 8);
    }
    // B: 1024 16B units (128 rows x 8 segs)
    #pragma unroll
    for (int i = 0; i < 2; i++) {
        int j = tid + i * 512;
        int row = j >> 3, seg = j & 7;
        cpa16(st + ABUF + row * XP + seg * 8, Bbase + (size_t)row * 1024 + ck * 64 + seg * 8);
    }
}

__global__ __launch_bounds__(512) void xgemm(int layer) {
    extern __shared__ __align__(16) __half xs[];
    const __half* W   = layer ? g_wih1 : g_wih0;
    const float* bias = layer ? g_bias1 : g_bias0;

    const int tid  = threadIdx.x;
    const int warp = tid >> 5, lane = tid & 31;
    const int wm = warp & 3, wn = warp >> 2;         // 4(m) x 4(n); warp tile 64x32
    const int mB = blockIdx.y, nB = blockIdx.x;
    const __half* Abase = g_ax + (size_t)(mB * 256) * 1024;
    const __half* Bbase = W   + (size_t)(nB * 128) * 1024;

    float acc[4][4][4] = {};

    const int arb = (lane & 7) + ((lane >> 3) & 1) * 8;
    const int ac  = (lane >> 4) * 8;
    const int brb = (lane & 7) + ((lane >> 4) & 1) * 8;
    const int bc  = ((lane >> 3) & 1) * 8;

    xload(xs,              Abase, Bbase, 0, tid); CPCOMMIT();
    xload(xs + XSTAGE,     Abase, Bbase, 1, tid); CPCOMMIT();
    xload(xs + 2 * XSTAGE, Abase, Bbase, 2, tid); CPCOMMIT();

    for (int ck = 0; ck < 16; ck++) {
        if (ck < 14)       CPWAIT(2);
        else if (ck == 14) CPWAIT(1);
        else               CPWAIT(0);
        __syncthreads();

        const int s = ck % 3;
        __half* Aa = xs + s * XSTAGE;
        __half* Bb = Aa + ABUF;

        #pragma unroll
        for (int k4 = 0; k4 < 4; k4++) {
            const int co = k4 * 16;
            unsigned aF[4][4];
            #pragma unroll
            for (int mb = 0; mb < 4; mb++) {
                int r = wm * 64 + mb * 16 + arb;
                ldsm4(aF[mb], Aa + r * XP + co + ac);
            }
            unsigned bF[4][2];
            #pragma unroll
            for (int p = 0; p < 2; p++) {
                int r = wn * 32 + p * 16 + brb;
                unsigned t[4];
                ldsm4(t, Bb + r * XP + co + bc);
                bF[2*p][0]=t[0]; bF[2*p][1]=t[1]; bF[2*p+1][0]=t[2]; bF[2*p+1][1]=t[3];
            }
            #pragma unroll
            for (int mb = 0; mb < 4; mb++)
                #pragma unroll
                for (int nb = 0; nb < 4; nb++)
                    mma_f16(acc[mb][nb], aF[mb], bF[nb][0], bF[nb][1]);
        }
        __syncthreads();

        if (ck + 3 < 16) { xload(xs + s * XSTAGE, Abase, Bbase, ck + 3, tid); CPCOMMIT(); }
    }

    #pragma unroll
    for (int mb = 0; mb < 4; mb++) {
        int r0 = mB * 256 + wm * 64 + mb * 16 + (lane >> 2);
        #pragma unroll
        for (int nb = 0; nb < 4; nb++) {
            int c0 = nB * 128 + wn * 32 + nb * 8 + 2 * (lane & 3);
            float b0 = bias[c0], b1 = bias[c0 + 1];
            size_t o0 = (size_t)r0 * GG + c0;
            size_t o1 = (size_t)(r0 + 8) * GG + c0;
            g_gx[o0]     = acc[mb][nb][0] + b0;
            g_gx[o0 + 1] = acc[mb][nb][1] + b1;
            g_gx[o1]     = acc[mb][nb][2] + b0;
            g_gx[o1 + 1] = acc[mb][nb][3] + b1;
        }
    }
}

// ---------------- persistent recurrence (512 threads, 2m x 8k warps) ----------------
// 128 CTAs x 512 thr. CTA ch owns h-cols [ch*8, ch*8+8) -> 32 gate rows in SMEM (fp16).
// Warp (wm = warp&1, wk = warp>>1): batch rows [wm*32, wm*32+32), K slice
// [wk*128, wk*128+128), ALL 32 gate columns. W smem duplication drops 4x -> 2x
// (the dominant recur term was ldsm traffic); A/h fragment reads stay unique.
#define WPITCH 1032
#define GSF    2112   // 64*33 floats per staging buffer
#define NKS    8      // K slices
#define RSMEM  (64 * WPITCH * 2 + NKS * GSF * 4)   // 132096 + 67584 = 199680
__global__ __launch_bounds__(512, 1) void recur(int layer, float* __restrict__ lastout) {
    extern __shared__ __align__(16) unsigned char sm[];
    __half* sWh = (__half*)sm;                      // [32][WPITCH] hi
    __half* sWl = (__half*)(sm + 32 * WPITCH * 2);  // [32][WPITCH] lo*1024
    float* gs = (float*)(sm + 64 * WPITCH * 2);     // [8][64][33]
    __shared__ unsigned sbase;

    const int tid  = threadIdx.x;
    const int warp = tid >> 5, lane = tid & 31;
    const int wm = warp & 1, wk = warp >> 1;        // 2 m-halves x 8 K-slices
    const int ch = blockIdx.x;
    const int j0 = ch * 8;
    const __half* W = layer ? g_whh1 : g_whh0;

    for (int idx = tid; idx < 32 * 128; idx += 512) {
        int n = idx >> 7, u = idx & 127;
        int g = (n >> 3) * 1024 + j0 + (n & 7);
        *(uint4*)(sWh + n * WPITCH + u * 8) = *(const uint4*)(W + (size_t)g * 2048 + u * 8);
        *(uint4*)(sWl + n * WPITCH + u * 8) = *(const uint4*)(W + (size_t)g * 2048 + 1024 + u * 8);
    }
    if (tid == 0) sbase = g_flags[ch];
    __syncthreads();
    const unsigned base = sbase;

    // consumer (GEMM) indices: A fragments for m-blocks {2wm, 2wm+1}, kt in [wk*8, wk*8+8)
    const int coffA0 = (2 * wm) * 8192 + (wk * 8) * 128 + lane * 4;
    const int coffA1 = coffA0 + 8192;
    const int brow = (lane & 7) + ((lane >> 4) & 1) * 8;
    const int bcc  = ((lane >> 3) & 1) * 8;
    const __half* sWh_l0 = sWh + brow * WPITCH + bcc + wk * 128;          // gate rows 0-15
    const __half* sWh_l1 = sWh + (16 + brow) * WPITCH + bcc + wk * 128;   // gate rows 16-31
    const __half* sWl_l0 = sWl + brow * WPITCH + bcc + wk * 128;
    const __half* sWl_l1 = sWl + (16 + brow) * WPITCH + bcc + wk * 128;
    float* gw = gs + wk * GSF;
    const float ILO = 1.0f / 1024.0f;

    // writer (elementwise) indices: threads 0-255, each -> (b, col, col+1)
    const int b  = (tid & 255) >> 2;
    const int jp = tid & 3;
    const int col = j0 + 2 * jp;
    const int widx = (b >> 4) * 8192 + (col >> 4) * 128
                   + ((((b & 7) << 2) | ((col >> 1) & 3)) << 2)
                   + ((col >> 3) & 1) * 2 + ((b >> 3) & 1);

    float c0 = 0.0f, c1 = 0.0f;   // cell state (threads 0-255 only)

    for (int t = 0; t < TT; t++) {
        float2 gx0, gx1, gx2, gx3;
        if (tid < 256) {
            const float* gx = g_gx + ((size_t)t * 64 + b) * GG + col;
            gx0 = *(const float2*)(gx);
            gx1 = *(const float2*)(gx + 1024);
            gx2 = *(const float2*)(gx + 2048);
            gx3 = *(const float2*)(gx + 3072);
        }

        float accH[2][4][4] = {}, accL[2][4][4] = {};
        if (t > 0) {
            const unsigned* hf = g_hf[(t & 1) ^ 1];
            #pragma unroll 4
            for (int k = 0; k < 8; k++) {
                unsigned aH0[4], aH1[4], b0h[4], b1h[4], b0l[4], b1l[4];
                ldg_cg4(aH0, hf + coffA0 + k * 128);
                ldg_cg4(aH1, hf + coffA1 + k * 128);
                ldsm4(b0h, sWh_l0 + k * 16);
                ldsm4(b1h, sWh_l1 + k * 16);
                ldsm4(b0l, sWl_l0 + k * 16);
                ldsm4(b1l, sWl_l1 + k * 16);
                mma_f16(accH[0][0], aH0, b0h[0], b0h[1]);
                mma_f16(accH[0][1], aH0, b0h[2], b0h[3]);
                mma_f16(accH[0][2], aH0, b1h[0], b1h[1]);
                mma_f16(accH[0][3], aH0, b1h[2], b1h[3]);
                mma_f16(accL[0][0], aH0, b0l[0], b0l[1]);
                mma_f16(accL[0][1], aH0, b0l[2], b0l[3]);
                mma_f16(accL[0][2], aH0, b1l[0], b1l[1]);
                mma_f16(accL[0][3], aH0, b1l[2], b1l[3]);
                mma_f16(accH[1][0], aH1, b0h[0], b0h[1]);
                mma_f16(accH[1][1], aH1, b0h[2], b0h[3]);
                mma_f16(accH[1][2], aH1, b1h[0], b1h[1]);
                mma_f16(accH[1][3], aH1, b1h[2], b1h[3]);
                mma_f16(accL[1][0], aH1, b0l[0], b0l[1]);
                mma_f16(accL[1][1], aH1, b0l[2], b0l[3]);
                mma_f16(accL[1][2], aH1, b1l[0], b1l[1]);
                mma_f16(accL[1][3], aH1, b1l[2], b1l[3]);
            }
        }

        // stage gate partial sums (hi + lo/1024) to this K-slice's buffer [64][33]
        {
            #pragma unroll
            for (int mb = 0; mb < 2; mb++) {
                int r = wm * 32 + mb * 16 + (lane >> 2);
                #pragma unroll
                for (int nb = 0; nb < 4; nb++) {
                    int c = nb * 8 + 2 * (lane & 3);
                    gw[r * 33 + c]           = accH[mb][nb][0] + accL[mb][nb][0] * ILO;
                    gw[r * 33 + c + 1]       = accH[mb][nb][1] + accL[mb][nb][1] * ILO;
                    gw[(r + 8) * 33 + c]     = accH[mb][nb][2] + accL[mb][nb][2] * ILO;
                    gw[(r + 8) * 33 + c + 1] = accH[mb][nb][3] + accL[mb][nb][3] * ILO;
                }
            }
        }
        __syncthreads();

        // LSTM elementwise: threads 0-255, 2 cells each (cols col, col+1)
        if (tid < 256) {
            #define SUM8(off) (((gs[(off)] + gs[GSF + (off)]) + (gs[2*GSF + (off)] + gs[3*GSF + (off)])) + \
                               ((gs[4*GSF + (off)] + gs[5*GSF + (off)]) + (gs[6*GSF + (off)] + gs[7*GSF + (off)])))
            float gi0 = SUM8(b * 33 + 2*jp)          + gx0.x;
            float gi1 = SUM8(b * 33 + 2*jp + 1)      + gx0.y;
            float gf0 = SUM8(b * 33 + 8 + 2*jp)      + gx1.x;
            float gf1 = SUM8(b * 33 + 8 + 2*jp + 1)  + gx1.y;
            float gg0 = SUM8(b * 33 + 16 + 2*jp)     + gx2.x;
            float gg1 = SUM8(b * 33 + 16 + 2*jp + 1) + gx2.y;
            float go0 = SUM8(b * 33 + 24 + 2*jp)     + gx3.x;
            float go1 = SUM8(b * 33 + 24 + 2*jp + 1) + gx3.y;
            #undef SUM8

            float i0 = sigf(gi0), f0 = sigf(gf0), G0 = tanhf(gg0), o0 = sigf(go0);
            float i1 = sigf(gi1), f1 = sigf(gf1), G1 = tanhf(gg1), o1 = sigf(go1);
            c0 = f0 * c0 + i0 * G0;
            c1 = f1 * c1 + i1 * G1;
            float hn0 = o0 * tanhf(c0);
            float hn1 = o1 * tanhf(c1);

            __half2 hh2 = __halves2half2(__float2half_rn(hn0), __float2half_rn(hn1));
            g_hf[t & 1][widx] = *(unsigned*)&hh2;
            if (layer == 0) {
                *(unsigned*)(g_ax + ((size_t)t * 64 + b) * 1024 + col) = *(unsigned*)&hh2;
            } else if (t == TT - 1) {
                lastout[b * HH + col]     = hn0;
                lastout[b * HH + col + 1] = hn1;
            }
        }

        // release: all threads' h stores ordered before flag; then hot-spin barrier.
        __threadfence();
        __syncthreads();
        const unsigned target = base + (unsigned)t + 1u;
        if (tid == 0) st_rel(&g_flags[ch], target);
        if (tid < 128) {
            while ((int)(ld_acq(&g_flags[tid]) - target) < 0) { }
        }
        __syncthreads();
        // no acquire fence needed: h reads use ld.cg (L2 is the coherence point)
    }
}

// ---------------- host launcher ----------------
extern "C" void kernel_launch(void* const* d_in, const int* in_sizes, int n_in,
                              void* d_out, int out_size) {
    (void)in_sizes; (void)n_in; (void)out_size;
    const float* x     = (const float*)d_in[0];
    const float* w_ih0 = (const float*)d_in[1];
    const float* w_hh0 = (const float*)d_in[2];
    const float* b_ih0 = (const float*)d_in[3];
    const float* b_hh0 = (const float*)d_in[4];
    const float* w_ih1 = (const float*)d_in[5];
    const float* w_hh1 = (const float*)d_in[6];
    const float* b_ih1 = (const float*)d_in[7];
    const float* b_hh1 = (const float*)d_in[8];
    const unsigned* m_ih0 = (const unsigned*)d_in[9];
    const unsigned* m_hh0 = (const unsigned*)d_in[10];
    const unsigned* m_ih1 = (const unsigned*)d_in[11];
    const unsigned* m_hh1 = (const unsigned*)d_in[12];
    float* out = (float*)d_out;

    cudaFuncSetAttribute(recur, cudaFuncAttributeMaxDynamicSharedMemorySize, RSMEM);
    cudaFuncSetAttribute(xgemm, cudaFuncAttributeMaxDynamicSharedMemorySize, XSMEM);

    prep_all<<<65537, 256>>>(w_ih0, m_ih0, w_hh0, m_hh0, w_ih1, m_ih1, w_hh1, m_hh1,
                             b_ih0, b_hh0, b_ih1, b_hh1);
    prep_ax<<<MTOT / 2, 256>>>(x);

    dim3 gemmGrid(GG / 128, MTOT / 256);   // (32, 128)

    xgemm<<<gemmGrid, 512, XSMEM>>>(0);
    recur<<<128, 512, RSMEM>>>(0, nullptr);   // also writes g_ax for layer 1

    xgemm<<<gemmGrid, 512, XSMEM>>>(1);
    recur<<<128, 512, RSMEM>>>(1, out);
}

// round 17
// speedup vs baseline: 1.6552x; 1.6552x over previous
#include <cuda_runtime.h>
#include <cuda_bf16.h>
#include <cuda_fp16.h>
#include <cstdint>

typedef __nv_bfloat16 bf16;

#define BSZ 64
#define TT  512
#define FF  1024
#define HH  1024
#define GG  4096
#define KK  1024
#define MTOT (TT*BSZ)   // 32768

// ---------------- device scratch ----------------
__device__ __align__(16) __half g_wih0[GG * KK];       // [G][K] fp16 single plane (xgemm)
__device__ __align__(16) __half g_wih1[GG * KK];
__device__ __align__(16) __half g_whh0[GG * 2 * KK];   // [G][hi | lo*1024] fp16 (recur)
__device__ __align__(16) __half g_whh1[GG * 2 * KK];
__device__ __align__(16) float  g_bias0[GG];
__device__ __align__(16) float  g_bias1[GG];
__device__ __align__(16) float  g_gx[(size_t)MTOT * GG];   // gates_x (512 MB)
__device__ __align__(16) __half g_ax[(size_t)MTOT * KK];   // fp16 A for xgemm (64 MB)
// h in mma-fragment layout (fp16x2, single plane):
//   u32 idx(mblk, kt, lane, reg) = mblk*8192 + kt*128 + lane*4 + reg
__device__ __align__(16) unsigned g_hf[2][32768];

// grid-barrier counters: monotonic, never reset; 256 releases per CTA per step.
__device__ unsigned g_cnt[128];

// ---------------- generic helpers ----------------
__device__ __forceinline__ void mma_f16(float acc[4], const unsigned a[4], unsigned b0, unsigned b1) {
    asm volatile(
        "mma.sync.aligned.m16n8k16.row.col.f32.f16.f16.f32 "
        "{%0,%1,%2,%3},{%4,%5,%6,%7},{%8,%9},{%0,%1,%2,%3};\n"
        : "+f"(acc[0]), "+f"(acc[1]), "+f"(acc[2]), "+f"(acc[3])
        : "r"(a[0]), "r"(a[1]), "r"(a[2]), "r"(a[3]), "r"(b0), "r"(b1));
}

__device__ __forceinline__ void ldsm4(unsigned r[4], const void* p) {
    unsigned addr = (unsigned)__cvta_generic_to_shared(p);
    asm volatile("ldmatrix.sync.aligned.m8n8.x4.shared.b16 {%0,%1,%2,%3},[%4];\n"
                 : "=r"(r[0]), "=r"(r[1]), "=r"(r[2]), "=r"(r[3]) : "r"(addr));
}

__device__ __forceinline__ void ldg_cg4(unsigned r[4], const void* p) {
    asm volatile("ld.global.cg.v4.u32 {%0,%1,%2,%3}, [%4];\n"
                 : "=r"(r[0]), "=r"(r[1]), "=r"(r[2]), "=r"(r[3]) : "l"(p));
}

__device__ __forceinline__ void red_add_rel(unsigned* p, unsigned v) {
    asm volatile("red.release.gpu.global.add.u32 [%0], %1;\n" :: "l"(p), "r"(v) : "memory");
}
__device__ __forceinline__ unsigned ld_acq(const unsigned* p) {
    unsigned v;
    asm volatile("ld.acquire.gpu.global.u32 %0, [%1];\n" : "=r"(v) : "l"(p) : "memory");
    return v;
}

__device__ __forceinline__ void cpa16(void* dst, const void* src) {
    unsigned d = (unsigned)__cvta_generic_to_shared(dst);
    asm volatile("cp.async.cg.shared.global [%0], [%1], 16;\n" :: "r"(d), "l"(src));
}
#define CPCOMMIT() asm volatile("cp.async.commit_group;\n")
#define CPWAIT(n)  asm volatile("cp.async.wait_group %0;\n" :: "n"(n))

__device__ __forceinline__ float sigf(float x) { return 1.0f / (1.0f + expf(-x)); }

// ---------------- prep: all weights + biases in ONE launch ----------------
__global__ void prep_all(const float* __restrict__ w0, const unsigned* __restrict__ m0,
                         const float* __restrict__ w1, const unsigned* __restrict__ m1,
                         const float* __restrict__ w2, const unsigned* __restrict__ m2,
                         const float* __restrict__ w3, const unsigned* __restrict__ m3,
                         const float* __restrict__ bi0, const float* __restrict__ bh0,
                         const float* __restrict__ bi1, const float* __restrict__ bh1) {
    int blk = blockIdx.x;
    if (blk < 65536) {
        int which = blk >> 14;
        int idx = (blk & 16383) * 256 + threadIdx.x;
        const float*    w = (which == 0) ? w0 : (which == 1) ? w1 : (which == 2) ? w2 : w3;
        const unsigned* m = (which == 0) ? m0 : (which == 1) ? m1 : (which == 2) ? m2 : m3;
        int g = idx >> 10, k = idx & 1023;
        float v = (m[idx] != 0u) ? w[idx] : 0.0f;
        __half hi = __float2half_rn(v);
        if (which == 1 || which == 3) {            // whh: 2-plane
            __half* dst = (which == 1) ? g_whh0 : g_whh1;
            float r = (v - __half2float(hi)) * 1024.0f;
            dst[(size_t)g * 2048 + k]        = hi;
            dst[(size_t)g * 2048 + 1024 + k] = __float2half_rn(r);
        } else {                                   // wih: single plane
            __half* dst = (which == 0) ? g_wih0 : g_wih1;
            dst[(size_t)g * 1024 + k] = hi;
        }
    } else {
        for (int i = threadIdx.x; i < GG; i += 256) {
            g_bias0[i] = bi0[i] + bh0[i];
            g_bias1[i] = bi1[i] + bh1[i];
        }
    }
}

// ---------------- prep: x -> g_ax fp16 rows (m = t*64 + b) ----------------
__global__ void prep_ax(const float* __restrict__ x) {
    int m = blockIdx.x * 2 + (threadIdx.x >> 7);
    int c = (threadIdx.x & 127) * 8;
    const float* src = x + ((size_t)(m & 63) * TT + (m >> 6)) * FF + c;
    float4 v0 = *(const float4*)src;
    float4 v1 = *(const float4*)(src + 4);
    __half2 h0 = __halves2half2(__float2half_rn(v0.x), __float2half_rn(v0.y));
    __half2 h1 = __halves2half2(__float2half_rn(v0.z), __float2half_rn(v0.w));
    __half2 h2 = __halves2half2(__float2half_rn(v1.x), __float2half_rn(v1.y));
    __half2 h3 = __halves2half2(__float2half_rn(v1.z), __float2half_rn(v1.w));
    *(uint4*)(g_ax + (size_t)m * 1024 + c) =
        make_uint4(*(unsigned*)&h0, *(unsigned*)&h1, *(unsigned*)&h2, *(unsigned*)&h3);
}

// ---------------- big input GEMM: gates_x = A @ W^T + bias (fp16 single product) ----------------
// CTA tile 256(M) x 128(N); 512 threads / 16 warps in 4(m) x 4(n); warp tile 64x32.
#define XP 72
#define ABUF (256 * XP)
#define BBUF (128 * XP)
#define XSTAGE (ABUF + BBUF)
#define XSMEM (3 * XSTAGE * 2)   // 165888

__device__ __forceinline__ void xload(__half* st, const __half* Abase, const __half* Bbase,
                                      int ck, int tid) {
    #pragma unroll
    for (int i = 0; i < 4; i++) {
        int j = tid + i * 512;
        int row = j >> 3, seg = j & 7;
        cpa16(st + row * XP + seg * 8, Abase + (size_t)row * 1024 + ck * 64 + seg * 8);
    }
    #pragma unroll
    for (int i = 0; i < 2; i++) {
        int j = tid + i * 512;
        int row = j >> 3, seg = j & 7;
        cpa16(st + ABUF + row * XP + seg * 8, Bbase + (size_t)row * 1024 + ck * 64 + seg * 8);
    }
}

__global__ __launch_bounds__(512) void xgemm(int layer) {
    extern __shared__ __align__(16) __half xs[];
    const __half* W   = layer ? g_wih1 : g_wih0;
    const float* bias = layer ? g_bias1 : g_bias0;

    const int tid  = threadIdx.x;
    const int warp = tid >> 5, lane = tid & 31;
    const int wm = warp & 3, wn = warp >> 2;
    const int mB = blockIdx.y, nB = blockIdx.x;
    const __half* Abase = g_ax + (size_t)(mB * 256) * 1024;
    const __half* Bbase = W   + (size_t)(nB * 128) * 1024;

    float acc[4][4][4] = {};

    const int arb = (lane & 7) + ((lane >> 3) & 1) * 8;
    const int ac  = (lane >> 4) * 8;
    const int brb = (lane & 7) + ((lane >> 4) & 1) * 8;
    const int bc  = ((lane >> 3) & 1) * 8;

    xload(xs,              Abase, Bbase, 0, tid); CPCOMMIT();
    xload(xs + XSTAGE,     Abase, Bbase, 1, tid); CPCOMMIT();
    xload(xs + 2 * XSTAGE, Abase, Bbase, 2, tid); CPCOMMIT();

    for (int ck = 0; ck < 16; ck++) {
        if (ck < 14)       CPWAIT(2);
        else if (ck == 14) CPWAIT(1);
        else               CPWAIT(0);
        __syncthreads();

        const int s = ck % 3;
        __half* Aa = xs + s * XSTAGE;
        __half* Bb = Aa + ABUF;

        #pragma unroll
        for (int k4 = 0; k4 < 4; k4++) {
            const int co = k4 * 16;
            unsigned aF[4][4];
            #pragma unroll
            for (int mb = 0; mb < 4; mb++) {
                int r = wm * 64 + mb * 16 + arb;
                ldsm4(aF[mb], Aa + r * XP + co + ac);
            }
            unsigned bF[4][2];
            #pragma unroll
            for (int p = 0; p < 2; p++) {
                int r = wn * 32 + p * 16 + brb;
                unsigned t[4];
                ldsm4(t, Bb + r * XP + co + bc);
                bF[2*p][0]=t[0]; bF[2*p][1]=t[1]; bF[2*p+1][0]=t[2]; bF[2*p+1][1]=t[3];
            }
            #pragma unroll
            for (int mb = 0; mb < 4; mb++)
                #pragma unroll
                for (int nb = 0; nb < 4; nb++)
                    mma_f16(acc[mb][nb], aF[mb], bF[nb][0], bF[nb][1]);
        }
        __syncthreads();

        if (ck + 3 < 16) { xload(xs + s * XSTAGE, Abase, Bbase, ck + 3, tid); CPCOMMIT(); }
    }

    #pragma unroll
    for (int mb = 0; mb < 4; mb++) {
        int r0 = mB * 256 + wm * 64 + mb * 16 + (lane >> 2);
        #pragma unroll
        for (int nb = 0; nb < 4; nb++) {
            int c0 = nB * 128 + wn * 32 + nb * 8 + 2 * (lane & 3);
            float b0 = bias[c0], b1 = bias[c0 + 1];
            size_t o0 = (size_t)r0 * GG + c0;
            size_t o1 = (size_t)(r0 + 8) * GG + c0;
            g_gx[o0]     = acc[mb][nb][0] + b0;
            g_gx[o0 + 1] = acc[mb][nb][1] + b1;
            g_gx[o1]     = acc[mb][nb][2] + b0;
            g_gx[o1 + 1] = acc[mb][nb][3] + b1;
        }
    }
}

// ---------------- persistent recurrence (512 threads, 4m x 4k warps; R15 shape) ----------------
// Barrier v3: writer threads (0-255) release-arrive via red.add.release.gpu on their CTA's
// counter right after their h stores (replaces per-thread __threadfence + flag store);
// pollers ld.acquire until counter = base + 256*(t+1). gx prefetch for t+1 hoisted
// BEFORE the arrival so its L2 latency hides under the barrier wait.
#define WPITCH 1032
#define GSF    2112   // 64*33 floats per staging buffer
#define RSMEM  (64 * WPITCH * 2 + 4 * GSF * 4)   // 165888
__global__ __launch_bounds__(512, 1) void recur(int layer, float* __restrict__ lastout) {
    extern __shared__ __align__(16) unsigned char sm[];
    __half* sWh = (__half*)sm;                      // [32][WPITCH] hi
    __half* sWl = (__half*)(sm + 32 * WPITCH * 2);  // [32][WPITCH] lo*1024
    float* gs = (float*)(sm + 64 * WPITCH * 2);     // [4][64][33]
    __shared__ unsigned sbase;

    const int tid  = threadIdx.x;
    const int warp = tid >> 5, lane = tid & 31;
    const int wm = warp & 3, wk = warp >> 2;        // 4 m-blocks x 4 K-slices
    const int ch = blockIdx.x;
    const int j0 = ch * 8;
    const __half* W = layer ? g_whh1 : g_whh0;

    for (int idx = tid; idx < 32 * 128; idx += 512) {
        int n = idx >> 7, u = idx & 127;
        int g = (n >> 3) * 1024 + j0 + (n & 7);
        *(uint4*)(sWh + n * WPITCH + u * 8) = *(const uint4*)(W + (size_t)g * 2048 + u * 8);
        *(uint4*)(sWl + n * WPITCH + u * 8) = *(const uint4*)(W + (size_t)g * 2048 + 1024 + u * 8);
    }
    if (tid == 0) sbase = g_cnt[ch];
    __syncthreads();
    const unsigned base = sbase;

    // consumer (GEMM) indices
    const int coff = wm * 8192 + lane * 4 + wk * 16 * 128;
    const int brow = (lane & 7) + ((lane >> 4) & 1) * 8;
    const int bcc  = ((lane >> 3) & 1) * 8;
    const __half* sWh_l0 = sWh + brow * WPITCH + bcc + wk * 16 * 16;
    const __half* sWh_l1 = sWh + (16 + brow) * WPITCH + bcc + wk * 16 * 16;
    const __half* sWl_l0 = sWl + brow * WPITCH + bcc + wk * 16 * 16;
    const __half* sWl_l1 = sWl + (16 + brow) * WPITCH + bcc + wk * 16 * 16;
    float* gw = gs + wk * GSF;
    const float ILO = 1.0f / 1024.0f;

    // writer (elementwise) indices: threads 0-255, each -> (b, col, col+1)
    const int b  = (tid & 255) >> 2;
    const int jp = tid & 3;
    const int col = j0 + 2 * jp;
    const int widx = (b >> 4) * 8192 + (col >> 4) * 128
                   + ((((b & 7) << 2) | ((col >> 1) & 3)) << 2)
                   + ((col >> 3) & 1) * 2 + ((b >> 3) & 1);

    float c0 = 0.0f, c1 = 0.0f;   // cell state (threads 0-255 only)

    // prefetch gx for t=0
    float2 gx0, gx1, gx2, gx3;
    if (tid < 256) {
        const float* gx = g_gx + (size_t)b * GG + col;
        gx0 = *(const float2*)(gx);
        gx1 = *(const float2*)(gx + 1024);
        gx2 = *(const float2*)(gx + 2048);
        gx3 = *(const float2*)(gx + 3072);
    }

    for (int t = 0; t < TT; t++) {
        float accH[4][4] = {}, accL[4][4] = {};
        if (t > 0) {
            const unsigned* hf = g_hf[(t & 1) ^ 1] + coff;
            #pragma unroll 4
            for (int k = 0; k < 16; k++) {
                unsigned aH[4], b0h[4], b1h[4], b0l[4], b1l[4];
                ldg_cg4(aH, hf + k * 128);
                ldsm4(b0h, sWh_l0 + k * 16);
                ldsm4(b1h, sWh_l1 + k * 16);
                ldsm4(b0l, sWl_l0 + k * 16);
                ldsm4(b1l, sWl_l1 + k * 16);
                mma_f16(accH[0], aH, b0h[0], b0h[1]);
                mma_f16(accH[1], aH, b0h[2], b0h[3]);
                mma_f16(accH[2], aH, b1h[0], b1h[1]);
                mma_f16(accH[3], aH, b1h[2], b1h[3]);
                mma_f16(accL[0], aH, b0l[0], b0l[1]);
                mma_f16(accL[1], aH, b0l[2], b0l[3]);
                mma_f16(accL[2], aH, b1l[0], b1l[1]);
                mma_f16(accL[3], aH, b1l[2], b1l[3]);
            }
        }

        // stage gate partial sums (hi + lo/1024) to this K-slice's buffer [64][33]
        {
            int r = wm * 16 + (lane >> 2);
            #pragma unroll
            for (int nb = 0; nb < 4; nb++) {
                int c = nb * 8 + 2 * (lane & 3);
                gw[r * 33 + c]           = accH[nb][0] + accL[nb][0] * ILO;
                gw[r * 33 + c + 1]       = accH[nb][1] + accL[nb][1] * ILO;
                gw[(r + 8) * 33 + c]     = accH[nb][2] + accL[nb][2] * ILO;
                gw[(r + 8) * 33 + c + 1] = accH[nb][3] + accL[nb][3] * ILO;
            }
        }
        __syncthreads();

        // LSTM elementwise: threads 0-255, 2 cells each (cols col, col+1)
        if (tid < 256) {
            #define SUM4(off) (gs[(off)] + gs[GSF + (off)] + gs[2*GSF + (off)] + gs[3*GSF + (off)])
            float gi0 = SUM4(b * 33 + 2*jp)          + gx0.x;
            float gi1 = SUM4(b * 33 + 2*jp + 1)      + gx0.y;
            float gf0 = SUM4(b * 33 + 8 + 2*jp)      + gx1.x;
            float gf1 = SUM4(b * 33 + 8 + 2*jp + 1)  + gx1.y;
            float gg0 = SUM4(b * 33 + 16 + 2*jp)     + gx2.x;
            float gg1 = SUM4(b * 33 + 16 + 2*jp + 1) + gx2.y;
            float go0 = SUM4(b * 33 + 24 + 2*jp)     + gx3.x;
            float go1 = SUM4(b * 33 + 24 + 2*jp + 1) + gx3.y;
            #undef SUM4

            float i0 = sigf(gi0), f0 = sigf(gf0), G0 = tanhf(gg0), o0 = sigf(go0);
            float i1 = sigf(gi1), f1 = sigf(gf1), G1 = tanhf(gg1), o1 = sigf(go1);
            c0 = f0 * c0 + i0 * G0;
            c1 = f1 * c1 + i1 * G1;
            float hn0 = o0 * tanhf(c0);
            float hn1 = o1 * tanhf(c1);

            __half2 hh2 = __halves2half2(__float2half_rn(hn0), __float2half_rn(hn1));
            g_hf[t & 1][widx] = *(unsigned*)&hh2;
            if (layer == 0) {
                *(unsigned*)(g_ax + ((size_t)t * 64 + b) * 1024 + col) = *(unsigned*)&hh2;
            } else if (t == TT - 1) {
                lastout[b * HH + col]     = hn0;
                lastout[b * HH + col + 1] = hn1;
            }

            // prefetch gx for t+1 BEFORE the barrier (hides L2 latency under the wait)
            if (t + 1 < TT) {
                const float* gx = g_gx + ((size_t)(t + 1) * 64 + b) * GG + col;
                gx0 = *(const float2*)(gx);
                gx1 = *(const float2*)(gx + 1024);
                gx2 = *(const float2*)(gx + 2048);
                gx3 = *(const float2*)(gx + 3072);
            }

            // release-arrival: orders THIS thread's h stores before the increment
            red_add_rel(&g_cnt[ch], 1u);
        }

        // barrier wait: counter i reaches base + 256*(t+1) once all its writers arrived
        const unsigned target = base + 256u * (unsigned)(t + 1);
        if (tid < 128) {
            while ((int)(ld_acq(&g_cnt[tid]) - target) < 0) { }
        }
        __syncthreads();
    }
}

// ---------------- host launcher ----------------
extern "C" void kernel_launch(void* const* d_in, const int* in_sizes, int n_in,
                              void* d_out, int out_size) {
    (void)in_sizes; (void)n_in; (void)out_size;
    const float* x     = (const float*)d_in[0];
    const float* w_ih0 = (const float*)d_in[1];
    const float* w_hh0 = (const float*)d_in[2];
    const float* b_ih0 = (const float*)d_in[3];
    const float* b_hh0 = (const float*)d_in[4];
    const float* w_ih1 = (const float*)d_in[5];
    const float* w_hh1 = (const float*)d_in[6];
    const float* b_ih1 = (const float*)d_in[7];
    const float* b_hh1 = (const float*)d_in[8];
    const unsigned* m_ih0 = (const unsigned*)d_in[9];
    const unsigned* m_hh0 = (const unsigned*)d_in[10];
    const unsigned* m_ih1 = (const unsigned*)d_in[11];
    const unsigned* m_hh1 = (const unsigned*)d_in[12];
    float* out = (float*)d_out;

    cudaFuncSetAttribute(recur, cudaFuncAttributeMaxDynamicSharedMemorySize, RSMEM);
    cudaFuncSetAttribute(xgemm, cudaFuncAttributeMaxDynamicSharedMemorySize, XSMEM);

    prep_all<<<65537, 256>>>(w_ih0, m_ih0, w_hh0, m_hh0, w_ih1, m_ih1, w_hh1, m_hh1,
                             b_ih0, b_hh0, b_ih1, b_hh1);
    prep_ax<<<MTOT / 2, 256>>>(x);

    dim3 gemmGrid(GG / 128, MTOT / 256);   // (32, 128)

    xgemm<<<gemmGrid, 512, XSMEM>>>(0);
    recur<<<128, 512, RSMEM>>>(0, nullptr);   // also writes g_ax for layer 1

    xgemm<<<gemmGrid, 512, XSMEM>>>(1);
    recur<<<128, 512, RSMEM>>>(1, out);
}